// round 10
// baseline (speedup 1.0000x reference)
#include <cuda_runtime.h>
#include <cuda_fp16.h>
#include <stdint.h>
#include <math.h>

#define BATCH   131072
#define FRAME   267
#define H1      512
#define LATENT  256
#define KCODES  1024
#define KP1     576      // padded concat K (534 -> 576, 523 -> 576)

// ---------------- weight arena offsets (elements) ----------------
#define OFF_W1   0u
#define OFF_W2   294912u      // +512*576
#define OFF_W3   557056u      // +512*512
#define OFF_WMU  819200u      // +512*512
#define OFF_W4   950272u      // +256*512
#define OFF_W5   1245184u     // +512*576
#define OFF_W6   1507328u     // +512*512
#define OFF_WO   1769472u     // +512*512
#define OFF_EMB  2031616u     // +512*512  (Wo padded to 512 rows for NT=256 tiles)
#define ARENA    2293760u     // +1024*256

// ---------------- scratch (allocation-free: __device__ globals) ----------------
__device__ __align__(16) __half g_wh[ARENA];
__device__ __align__(16) __half g_wl[ARENA];
__device__ __align__(16) __half g_sh[(size_t)BATCH * KP1];
__device__ __align__(16) __half g_sl[(size_t)BATCH * KP1];
__device__ __align__(16) __half g_xh[(size_t)BATCH * H1];
__device__ __align__(16) __half g_xl[(size_t)BATCH * H1];
__device__ __align__(16) __half g_yh[(size_t)BATCH * H1];
__device__ __align__(16) __half g_yl[(size_t)BATCH * H1];
__device__ __align__(16) float  g_embTf[KCODES * LATENT];   // fp32 embed^T [k][l]
__device__ float  g_enorm[KCODES];
__device__ int    g_ind[BATCH];
__device__ unsigned g_counts[KCODES];
__device__ double g_loss;

// ---------------- helpers ----------------
__device__ __forceinline__ uint32_t smem_u32(const void* p) {
    uint32_t a;
    asm("{ .reg .u64 t; cvta.to.shared.u64 t, %1; cvt.u32.u64 %0, t; }" : "=r"(a) : "l"(p));
    return a;
}
__device__ __forceinline__ void ldsm4(uint32_t* r, uint32_t addr) {
    asm volatile("ldmatrix.sync.aligned.m8n8.x4.shared.b16 {%0,%1,%2,%3}, [%4];"
                 : "=r"(r[0]), "=r"(r[1]), "=r"(r[2]), "=r"(r[3]) : "r"(addr));
}
__device__ __forceinline__ void mma16816(float* c, const uint32_t* a, uint32_t b0, uint32_t b1) {
    asm volatile("mma.sync.aligned.m16n8k16.row.col.f32.f16.f16.f32 "
                 "{%0,%1,%2,%3}, {%4,%5,%6,%7}, {%8,%9}, {%0,%1,%2,%3};"
                 : "+f"(c[0]), "+f"(c[1]), "+f"(c[2]), "+f"(c[3])
                 : "r"(a[0]), "r"(a[1]), "r"(a[2]), "r"(a[3]), "r"(b0), "r"(b1));
}
__device__ __forceinline__ void cpa16(uint32_t dst, const void* src) {
    asm volatile("cp.async.cg.shared.global [%0], [%1], 16;" :: "r"(dst), "l"(src));
}
#define CPA_COMMIT() asm volatile("cp.async.commit_group;" ::: "memory")
#define CPA_WAIT1()  asm volatile("cp.async.wait_group 1;" ::: "memory")
__device__ __forceinline__ uint32_t pack2(__half a, __half b) {
    return (uint32_t)__half_as_ushort(a) | ((uint32_t)__half_as_ushort(b) << 16);
}
__device__ __forceinline__ void split2(float v, __half& h, __half& l) {
    h = __float2half_rn(v);
    l = __float2half_rn(v - __half2float(h));
}

// ---------------- init ----------------
__global__ void init_kernel() {
    int t = threadIdx.x;
    if (t < KCODES) g_counts[t] = 0u;
    if (t == 0) g_loss = 0.0;
}

// ---------------- embed norms + fp32 transpose ----------------
__global__ void enorm_kernel(const float* __restrict__ embed) {
    int k = blockIdx.x, l = threadIdx.x;           // k: code, l: latent dim
    float v = embed[l * KCODES + k];
    g_embTf[k * LATENT + l] = v;
    __shared__ float red[256];
    red[l] = v * v;
    __syncthreads();
    for (int s = 128; s > 0; s >>= 1) { if (l < s) red[l] += red[l + s]; __syncthreads(); }
    if (l == 0) g_enorm[k] = red[0];
}

// ---------------- weight prep: W[K][N] fp32 -> Wt[Npad][Kpad] fp16 h/l ----------------
__global__ void prep_w(const float* __restrict__ W, int K, int N, int Kpad, int Npad, unsigned off) {
    __shared__ float t[32][33];
    int k0 = blockIdx.x * 32, n0 = blockIdx.y * 32;
    int tx = threadIdx.x, ty = threadIdx.y;  // 32 x 8
    #pragma unroll
    for (int r = 0; r < 32; r += 8) {
        int k = k0 + ty + r, n = n0 + tx;
        t[ty + r][tx] = (k < K && n < N) ? W[(size_t)k * N + n] : 0.f;
    }
    __syncthreads();
    #pragma unroll
    for (int r = 0; r < 32; r += 8) {
        int n = n0 + ty + r, k = k0 + tx;
        if (n < Npad && k < Kpad) {
            __half h, l;
            split2(t[tx][ty + r], h, l);
            size_t o = off + (size_t)n * Kpad + k;
            g_wh[o] = h; g_wl[o] = l;
        }
    }
}

// ---------------- encoder input: [x | c | 0pad] -> fp16 h/l ----------------
__global__ void prep_xc(const float* __restrict__ x, const float* __restrict__ c) {
    int b = blockIdx.x, j = threadIdx.x;  // 576 threads
    float v = 0.f;
    if (j < FRAME)            v = x[(size_t)b * FRAME + j];
    else if (j < 2 * FRAME)   v = c[(size_t)b * FRAME + (j - FRAME)];
    __half h, l;
    split2(v, h, l);
    size_t o = (size_t)b * KP1 + j;
    g_sh[o] = h; g_sl[o] = l;
}

// =====================================================================
// fp16x2 tensor-core GEMM: C[128x256] = A[128 x Kpad] @ Wt^T   (Wt: [Npad][Kpad])
// 512 threads, 16 warps (4x4), warp tile 32x64, products hh+hl+lh, fp32 accum.
// MODE 0: relu + fp16-split out.  MODE 1: fp16-split out (no relu).
// MODE 2: fp32 out masked to N cols.
// cp.async 2-stage double buffering.
// =====================================================================
template<int MODE>
__global__ __launch_bounds__(512)
void mma_gemm(const __half* __restrict__ Ah, const __half* __restrict__ Al,
              int Kpad, unsigned woff, const float* __restrict__ bias, int N,
              __half* __restrict__ O0, __half* __restrict__ O1,
              float* __restrict__ Of, int ldo)
{
    extern __shared__ __align__(16) char smem[];
    const uint32_t sb = smem_u32(smem);
    const int tid = threadIdx.x, lane = tid & 31, wid = tid >> 5;
    const int warp_m = wid & 3, warp_n = wid >> 2;          // 4 x 4
    const int rowBlk = blockIdx.y * 128, colBlk = blockIdx.x * 256;
    constexpr uint32_t TA = 128 * 72 * 2;        // 18432 B
    constexpr uint32_t TB = 256 * 72 * 2;        // 36864 B
    constexpr uint32_t STAGE = 2 * TA + 2 * TB;  // 110592 B
    const uint32_t OS = 1024;                    // after bias[256]
    float* sbias = (float*)smem;

    if (tid < 256) {
        int gn = colBlk + tid;
        sbias[tid] = (gn < N) ? bias[gn] : 0.f;
    }

    const __half* Wh = g_wh + woff;
    const __half* Wl = g_wl + woff;

    // ---- stage loader: {Ah, Al, Bh, Bl} for chunk kc into stage st ----
    auto load_chunk = [&](int kc, int st) {
        uint32_t base = sb + OS + (uint32_t)st * STAGE;
        #pragma unroll
        for (int it = 0; it < 4; it++) {         // A: 2 splits x 128 rows x 8 q
            int i = tid + it * 512;
            int s = i >> 10, rem = i & 1023;
            int r = rem >> 3, q = rem & 7;
            uint32_t dst = base + (uint32_t)s * TA + (uint32_t)(r * 144 + q * 16);
            const __half* src = (s ? Al : Ah) + (size_t)(rowBlk + r) * Kpad + kc * 64 + q * 8;
            cpa16(dst, src);
        }
        #pragma unroll
        for (int it = 0; it < 8; it++) {         // B: 2 splits x 256 rows x 8 q
            int i = tid + it * 512;
            int s = i >> 11, rem = i & 2047;
            int r = rem >> 3, q = rem & 7;
            uint32_t dst = base + 2 * TA + (uint32_t)s * TB + (uint32_t)(r * 144 + q * 16);
            const __half* src = (s ? Wl : Wh) + (size_t)(colBlk + r) * Kpad + kc * 64 + q * 8;
            cpa16(dst, src);
        }
    };

    float acc[2][8][4];
    #pragma unroll
    for (int a = 0; a < 2; a++)
        #pragma unroll
        for (int b = 0; b < 8; b++)
            #pragma unroll
            for (int d = 0; d < 4; d++) acc[a][b][d] = 0.f;

    const int a_row  = (lane & 7) + ((lane >> 3) & 1) * 8;
    const int a_koff = ((lane >> 4) & 1) * 8;
    const int b_row  = (lane & 7) + ((lane >> 4) & 1) * 8;
    const int b_koff = ((lane >> 3) & 1) * 8;

    const int nch = Kpad >> 6;
    load_chunk(0, 0);
    CPA_COMMIT();

    for (int kc = 0; kc < nch; kc++) {
        if (kc + 1 < nch) load_chunk(kc + 1, (kc + 1) & 1);
        CPA_COMMIT();
        CPA_WAIT1();
        __syncthreads();
        const uint32_t stg = sb + OS + (uint32_t)(kc & 1) * STAGE;
        #pragma unroll
        for (int ks = 0; ks < 4; ks++) {
            uint32_t af[2][2][4];
            #pragma unroll
            for (int s = 0; s < 2; s++)
                #pragma unroll
                for (int mt = 0; mt < 2; mt++)
                    ldsm4(af[s][mt], stg + s * TA +
                          (uint32_t)((warp_m * 32 + mt * 16 + a_row) * 72 + ks * 16 + a_koff) * 2);
            #pragma unroll
            for (int nn = 0; nn < 4; nn++) {
                uint32_t bf[2][4];
                #pragma unroll
                for (int s = 0; s < 2; s++)
                    ldsm4(bf[s], stg + 2 * TA + s * TB +
                          (uint32_t)((warp_n * 64 + nn * 16 + b_row) * 72 + ks * 16 + b_koff) * 2);
                #pragma unroll
                for (int mt = 0; mt < 2; mt++)
                    #pragma unroll
                    for (int g = 0; g < 2; g++) {
                        float* c = acc[mt][nn * 2 + g];
                        mma16816(c, af[0][mt], bf[0][2 * g], bf[0][2 * g + 1]);   // hh
                        mma16816(c, af[0][mt], bf[1][2 * g], bf[1][2 * g + 1]);   // hl
                        mma16816(c, af[1][mt], bf[0][2 * g], bf[0][2 * g + 1]);   // lh
                    }
            }
        }
        __syncthreads();
    }

    // epilogue
    #pragma unroll
    for (int mt = 0; mt < 2; mt++) {
        const int row = rowBlk + warp_m * 32 + mt * 16 + (lane >> 2);
        #pragma unroll
        for (int g = 0; g < 8; g++) {
            const int colL = warp_n * 64 + g * 8 + 2 * (lane & 3);
            const int col = colBlk + colL;
            const float bz0 = sbias[colL], bz1 = sbias[colL + 1];
            const float* c = acc[mt][g];
            #pragma unroll
            for (int hf = 0; hf < 2; hf++) {
                const int r = row + hf * 8;
                float v0 = c[hf * 2] + bz0, v1 = c[hf * 2 + 1] + bz1;
                if (MODE == 0 || MODE == 1) {
                    if (MODE == 0) { v0 = fmaxf(v0, 0.f); v1 = fmaxf(v1, 0.f); }
                    __half h0, l0, h1, l1;
                    split2(v0, h0, l0);
                    split2(v1, h1, l1);
                    size_t o = (size_t)r * ldo + col;
                    *(uint32_t*)(O0 + o) = pack2(h0, h1);
                    *(uint32_t*)(O1 + o) = pack2(l0, l1);
                } else {
                    if (col < N)     Of[(size_t)r * ldo + col] = v0;
                    if (col + 1 < N) Of[(size_t)r * ldo + col + 1] = v1;
                }
            }
        }
    }
}

// =====================================================================
// VQ: per-row argmin over 1024 codes; dist = ||e||^2 - 2 mu.e
// mu A-tiles (2 splits x 4 chunks) resident in smem; embed B double-buffered.
// 256 threads, warp grid 4x2.
// =====================================================================
__global__ __launch_bounds__(256)
void vq_kernel()
{
    extern __shared__ __align__(16) char smem[];
    const uint32_t sb = smem_u32(smem);
    const int tid = threadIdx.x, lane = tid & 31, wid = tid >> 5;
    const int warp_m = wid & 3, warp_n = wid >> 2;
    const int rowBlk = blockIdx.x * 128;
    constexpr uint32_t TILE = 128 * 72 * 2;
    float* sval = (float*)smem;                    // [128]
    int*   sidx = (int*)(smem + 512);              // [128]
    const uint32_t OA = 1024;                      // A: [s][kc] 8 tiles
    const uint32_t OB = OA + 8 * TILE;             // B: 2 stages x {h,l}

    const int a_row  = (lane & 7) + ((lane >> 3) & 1) * 8;
    const int a_koff = ((lane >> 4) & 1) * 8;
    const int b_row  = (lane & 7) + ((lane >> 4) & 1) * 8;
    const int b_koff = ((lane >> 3) & 1) * 8;

    // ---- preload resident A (mu splits), all 4 chunks ----
    #pragma unroll
    for (int kc = 0; kc < 4; kc++)
        #pragma unroll
        for (int it = 0; it < 4; it++) {
            int i = tid + it * 256;
            int r = i >> 3, q = i & 7;
            size_t ga = (size_t)(rowBlk + r) * LATENT + kc * 64 + q * 8;
            uint32_t dst = sb + OA + (uint32_t)kc * TILE + (uint32_t)(r * 144 + q * 16);
            cpa16(dst,            g_yh + ga);
            cpa16(dst + 4 * TILE, g_yl + ga);
        }
    CPA_COMMIT();

    auto load_b = [&](int ct, int kc, int st) {
        uint32_t base = sb + OB + (uint32_t)st * 2 * TILE;
        #pragma unroll
        for (int it = 0; it < 4; it++) {
            int i = tid + it * 256;
            int r = i >> 3, q = i & 7;
            size_t gb = OFF_EMB + (size_t)(ct * 128 + r) * LATENT + kc * 64 + q * 8;
            uint32_t dst = base + (uint32_t)(r * 144 + q * 16);
            cpa16(dst,        g_wh + gb);
            cpa16(dst + TILE, g_wl + gb);
        }
    };

    load_b(0, 0, 0);
    CPA_COMMIT();

    float bv[4];
    int   bi[4];
    #pragma unroll
    for (int s = 0; s < 4; s++) { bv[s] = 3.4e38f; bi[s] = 0; }

    int gstep = 0;
    for (int ct = 0; ct < 8; ct++) {
        float acc[2][8][4];
        #pragma unroll
        for (int a = 0; a < 2; a++)
            #pragma unroll
            for (int b = 0; b < 8; b++)
                #pragma unroll
                for (int d = 0; d < 4; d++) acc[a][b][d] = 0.f;

        for (int kc = 0; kc < 4; kc++) {
            int nct = (kc + 1 < 4) ? ct : ct + 1;
            int nkc = (kc + 1 < 4) ? kc + 1 : 0;
            if (nct < 8) load_b(nct, nkc, (gstep + 1) & 1);
            CPA_COMMIT();
            CPA_WAIT1();
            __syncthreads();
            const uint32_t stg = sb + OB + (uint32_t)(gstep & 1) * 2 * TILE;
            #pragma unroll
            for (int ks = 0; ks < 4; ks++) {
                uint32_t af[2][2][4];
                #pragma unroll
                for (int s = 0; s < 2; s++)
                    #pragma unroll
                    for (int mt = 0; mt < 2; mt++)
                        ldsm4(af[s][mt], sb + OA + (uint32_t)(s * 4 + kc) * TILE +
                              (uint32_t)((warp_m * 32 + mt * 16 + a_row) * 72 + ks * 16 + a_koff) * 2);
                #pragma unroll
                for (int nn = 0; nn < 4; nn++) {
                    uint32_t bf[2][4];
                    #pragma unroll
                    for (int s = 0; s < 2; s++)
                        ldsm4(bf[s], stg + s * TILE +
                              (uint32_t)((warp_n * 64 + nn * 16 + b_row) * 72 + ks * 16 + b_koff) * 2);
                    #pragma unroll
                    for (int mt = 0; mt < 2; mt++)
                        #pragma unroll
                        for (int g = 0; g < 2; g++) {
                            float* c = acc[mt][nn * 2 + g];
                            mma16816(c, af[0][mt], bf[0][2 * g], bf[0][2 * g + 1]);
                            mma16816(c, af[0][mt], bf[1][2 * g], bf[1][2 * g + 1]);
                            mma16816(c, af[1][mt], bf[0][2 * g], bf[0][2 * g + 1]);
                        }
                }
            }
            gstep++;
            __syncthreads();
        }

        // ---- argmin epilogue for this code tile ----
        #pragma unroll
        for (int mt = 0; mt < 2; mt++)
            #pragma unroll
            for (int hf = 0; hf < 2; hf++) {
                const int slot = mt * 2 + hf;
                const int rowL = warp_m * 32 + mt * 16 + hf * 8 + (lane >> 2);
                float v = 3.4e38f; int idx = 0;
                #pragma unroll
                for (int g = 0; g < 8; g++)
                    #pragma unroll
                    for (int j = 0; j < 2; j++) {
                        int colL = warp_n * 64 + g * 8 + 2 * (lane & 3) + j;
                        int code = ct * 128 + colL;
                        float d = g_enorm[code] - 2.f * acc[mt][g][hf * 2 + j];
                        if (d < v || (d == v && code < idx)) { v = d; idx = code; }
                    }
                #pragma unroll
                for (int o = 1; o <= 2; o <<= 1) {
                    float ov = __shfl_xor_sync(0xFFFFFFFFu, v, o);
                    int   oi = __shfl_xor_sync(0xFFFFFFFFu, idx, o);
                    if (ov < v || (ov == v && oi < idx)) { v = ov; idx = oi; }
                }
                if (warp_n == 1 && (lane & 3) == 0) { sval[rowL] = v; sidx[rowL] = idx; }
                __syncthreads();
                if (warp_n == 0 && (lane & 3) == 0) {
                    float ov = sval[rowL]; int oi = sidx[rowL];
                    if (ov < v || (ov == v && oi < idx)) { v = ov; idx = oi; }
                    if (v < bv[slot] || (v == bv[slot] && idx < bi[slot])) { bv[slot] = v; bi[slot] = idx; }
                }
                __syncthreads();
            }
    }

    if (warp_n == 0 && (lane & 3) == 0) {
        #pragma unroll
        for (int mt = 0; mt < 2; mt++)
            #pragma unroll
            for (int hf = 0; hf < 2; hf++) {
                const int slot = mt * 2 + hf;
                const int rowL = warp_m * 32 + mt * 16 + hf * 8 + (lane >> 2);
                g_ind[rowBlk + rowL] = bi[slot];
                atomicAdd(&g_counts[bi[slot]], 1u);
            }
    }
}

// ---------------- gather quantize -> decoder input [q | c | 0pad] + loss ----------------
__global__ void gather_kernel(const float* __restrict__ c) {
    int b = blockIdx.x, j = threadIdx.x;   // 576 threads
    __shared__ float red[256];
    int k = g_ind[b];
    float v = 0.f;
    if (j < LATENT) {
        size_t om = (size_t)b * LATENT + j;
        float m = __half2float(g_yh[om]) + __half2float(g_yl[om]);
        float q = g_embTf[k * LATENT + j];
        float d = q - m;
        red[j] = d * d;
        v = q;
    } else if (j < LATENT + FRAME) {
        v = c[(size_t)b * FRAME + (j - LATENT)];
    }
    __half h, l;
    split2(v, h, l);
    size_t o = (size_t)b * KP1 + j;
    g_sh[o] = h; g_sl[o] = l;
    __syncthreads();
    for (int s = 128; s > 0; s >>= 1) { if (j < s) red[j] += red[j + s]; __syncthreads(); }
    if (j == 0) atomicAdd(&g_loss, (double)red[0]);
}

// ---------------- finalize scalars ----------------
__global__ void finalize_kernel(float* __restrict__ out) {
    __shared__ double red[1024];
    int t = threadIdx.x;
    double p = (double)g_counts[t] / (double)BATCH;
    red[t] = p * log(p + 1e-10);
    __syncthreads();
    for (int s = 512; s > 0; s >>= 1) { if (t < s) red[t] += red[t + s]; __syncthreads(); }
    if (t == 0) {
        size_t off = (size_t)BATCH * FRAME;
        out[off]     = (float)(g_loss / ((double)BATCH * (double)LATENT));
        out[off + 1] = (float)exp(-red[0]);
    }
}

// ---------------- launch ----------------
extern "C" void kernel_launch(void* const* d_in, const int* in_sizes, int n_in,
                              void* d_out, int out_size)
{
    const float* x    = (const float*)d_in[0];
    const float* c    = (const float*)d_in[1];
    const float* W1   = (const float*)d_in[2];  const float* b1  = (const float*)d_in[3];
    const float* W2   = (const float*)d_in[4];  const float* b2  = (const float*)d_in[5];
    const float* W3   = (const float*)d_in[6];  const float* b3  = (const float*)d_in[7];
    const float* Wmu  = (const float*)d_in[8];  const float* bmu = (const float*)d_in[9];
    const float* W4   = (const float*)d_in[10]; const float* b4  = (const float*)d_in[11];
    const float* W5   = (const float*)d_in[12]; const float* b5  = (const float*)d_in[13];
    const float* W6   = (const float*)d_in[14]; const float* b6  = (const float*)d_in[15];
    const float* Wo   = (const float*)d_in[16]; const float* bo  = (const float*)d_in[17];
    const float* embed= (const float*)d_in[18];
    float* out = (float*)d_out;

    __half *sh, *sl, *xh, *xl, *yh, *yl;
    cudaGetSymbolAddress((void**)&sh, g_sh);
    cudaGetSymbolAddress((void**)&sl, g_sl);
    cudaGetSymbolAddress((void**)&xh, g_xh);
    cudaGetSymbolAddress((void**)&xl, g_xl);
    cudaGetSymbolAddress((void**)&yh, g_yh);
    cudaGetSymbolAddress((void**)&yl, g_yl);

    const int SMG = 1024 + 2 * 110592;                 // 222208
    const int SMV = 1024 + 8 * 18432 + 2 * 2 * 18432;  // 222208
    cudaFuncSetAttribute((const void*)mma_gemm<0>, cudaFuncAttributeMaxDynamicSharedMemorySize, SMG);
    cudaFuncSetAttribute((const void*)mma_gemm<1>, cudaFuncAttributeMaxDynamicSharedMemorySize, SMG);
    cudaFuncSetAttribute((const void*)mma_gemm<2>, cudaFuncAttributeMaxDynamicSharedMemorySize, SMG);
    cudaFuncSetAttribute((const void*)vq_kernel,   cudaFuncAttributeMaxDynamicSharedMemorySize, SMV);

    const int MT = BATCH / 128;   // 1024 row tiles
    dim3 tb(32, 8);

    init_kernel<<<1, 1024>>>();
    enorm_kernel<<<KCODES, 256>>>(embed);

    // weight prep (transpose + fp16 2-way split), grid = (Kpad/32, Npad/32)
    prep_w<<<dim3(18, 16), tb>>>(W1,  534, 512,  KP1, 512,  OFF_W1);
    prep_w<<<dim3(16, 16), tb>>>(W2,  512, 512,  512, 512,  OFF_W2);
    prep_w<<<dim3(16, 16), tb>>>(W3,  512, 512,  512, 512,  OFF_W3);
    prep_w<<<dim3(16, 8),  tb>>>(Wmu, 512, 256,  512, 256,  OFF_WMU);
    prep_w<<<dim3(18, 16), tb>>>(W4,  523, 512,  KP1, 512,  OFF_W4);
    prep_w<<<dim3(16, 16), tb>>>(W5,  512, 512,  512, 512,  OFF_W5);
    prep_w<<<dim3(16, 16), tb>>>(W6,  512, 512,  512, 512,  OFF_W6);
    prep_w<<<dim3(16, 16), tb>>>(Wo,  512, 267,  512, 512,  OFF_WO);
    prep_w<<<dim3(8,  32), tb>>>(embed, 256, 1024, 256, 1024, OFF_EMB);

    prep_xc<<<BATCH, KP1>>>(x, c);

    // encoder
    mma_gemm<0><<<dim3(2, MT), 512, SMG>>>(sh, sl, KP1, OFF_W1,  b1,  512, xh, xl, nullptr, 512);
    mma_gemm<0><<<dim3(2, MT), 512, SMG>>>(xh, xl, 512, OFF_W2,  b2,  512, yh, yl, nullptr, 512);
    mma_gemm<0><<<dim3(2, MT), 512, SMG>>>(yh, yl, 512, OFF_W3,  b3,  512, xh, xl, nullptr, 512);
    mma_gemm<1><<<dim3(1, MT), 512, SMG>>>(xh, xl, 512, OFF_WMU, bmu, 256, yh, yl, nullptr, 256);  // mu splits

    // vector quantizer + gather/loss (rebuilds g_s as decoder input)
    vq_kernel<<<MT, 256, SMV>>>();
    gather_kernel<<<BATCH, KP1>>>(c);

    // decoder
    mma_gemm<0><<<dim3(2, MT), 512, SMG>>>(sh, sl, KP1, OFF_W4, b4, 512, xh, xl, nullptr, 512);
    mma_gemm<0><<<dim3(2, MT), 512, SMG>>>(xh, xl, 512, OFF_W5, b5, 512, yh, yl, nullptr, 512);
    mma_gemm<0><<<dim3(2, MT), 512, SMG>>>(yh, yl, 512, OFF_W6, b6, 512, xh, xl, nullptr, 512);
    mma_gemm<2><<<dim3(2, MT), 512, SMG>>>(xh, xl, 512, OFF_WO, bo, 267, nullptr, nullptr, out, FRAME);

    finalize_kernel<<<1, 1024>>>(out);
}

// round 11
// speedup vs baseline: 1.2251x; 1.2251x over previous
#include <cuda_runtime.h>
#include <cuda_fp16.h>
#include <stdint.h>
#include <math.h>

#define BATCH   131072
#define FRAME   267
#define H1      512
#define LATENT  256
#define KCODES  1024
#define KP1     576      // padded concat K (534 -> 576, 523 -> 576)

// ---------------- weight arena offsets (elements) ----------------
#define OFF_W1   0u
#define OFF_W2   294912u      // +512*576
#define OFF_W3   557056u      // +512*512
#define OFF_WMU  819200u      // +512*512
#define OFF_W4   950272u      // +256*512
#define OFF_W5   1245184u     // +512*576
#define OFF_W6   1507328u     // +512*512
#define OFF_WO   1769472u     // +512*512
#define OFF_EMB  1966080u     // +384*512 (Wo padded to 384 rows)
#define ARENA    2228224u     // +1024*256

// ---------------- scratch (allocation-free: __device__ globals) ----------------
__device__ __align__(16) __half g_wh[ARENA];
__device__ __align__(16) __half g_wl[ARENA];
__device__ __align__(16) __half g_sh[(size_t)BATCH * KP1];
__device__ __align__(16) __half g_sl[(size_t)BATCH * KP1];
__device__ __align__(16) __half g_xh[(size_t)BATCH * H1];
__device__ __align__(16) __half g_xl[(size_t)BATCH * H1];
__device__ __align__(16) __half g_yh[(size_t)BATCH * H1];
__device__ __align__(16) __half g_yl[(size_t)BATCH * H1];
__device__ __align__(16) float  g_embTf[KCODES * LATENT];   // fp32 embed^T [k][l]
__device__ float  g_enorm[KCODES];
__device__ int    g_ind[BATCH];
__device__ unsigned g_counts[KCODES];
__device__ double g_loss;

// ---------------- helpers ----------------
__device__ __forceinline__ uint32_t smem_u32(const void* p) {
    uint32_t a;
    asm("{ .reg .u64 t; cvta.to.shared.u64 t, %1; cvt.u32.u64 %0, t; }" : "=r"(a) : "l"(p));
    return a;
}
__device__ __forceinline__ void ldsm4(uint32_t* r, uint32_t addr) {
    asm volatile("ldmatrix.sync.aligned.m8n8.x4.shared.b16 {%0,%1,%2,%3}, [%4];"
                 : "=r"(r[0]), "=r"(r[1]), "=r"(r[2]), "=r"(r[3]) : "r"(addr));
}
__device__ __forceinline__ void mma16816(float* c, const uint32_t* a, uint32_t b0, uint32_t b1) {
    asm volatile("mma.sync.aligned.m16n8k16.row.col.f32.f16.f16.f32 "
                 "{%0,%1,%2,%3}, {%4,%5,%6,%7}, {%8,%9}, {%0,%1,%2,%3};"
                 : "+f"(c[0]), "+f"(c[1]), "+f"(c[2]), "+f"(c[3])
                 : "r"(a[0]), "r"(a[1]), "r"(a[2]), "r"(a[3]), "r"(b0), "r"(b1));
}
__device__ __forceinline__ void cpa16(uint32_t dst, const void* src) {
    asm volatile("cp.async.cg.shared.global [%0], [%1], 16;" :: "r"(dst), "l"(src));
}
#define CPA_COMMIT() asm volatile("cp.async.commit_group;" ::: "memory")
#define CPA_WAIT1()  asm volatile("cp.async.wait_group 1;" ::: "memory")
__device__ __forceinline__ uint32_t pack2(__half a, __half b) {
    return (uint32_t)__half_as_ushort(a) | ((uint32_t)__half_as_ushort(b) << 16);
}
__device__ __forceinline__ void split2(float v, __half& h, __half& l) {
    h = __float2half_rn(v);
    l = __float2half_rn(v - __half2float(h));
}

// ---------------- init ----------------
__global__ void init_kernel() {
    int t = threadIdx.x;
    if (t < KCODES) g_counts[t] = 0u;
    if (t == 0) g_loss = 0.0;
}

// ---------------- embed norms + fp32 transpose ----------------
__global__ void enorm_kernel(const float* __restrict__ embed) {
    int k = blockIdx.x, l = threadIdx.x;           // k: code, l: latent dim
    float v = embed[l * KCODES + k];
    g_embTf[k * LATENT + l] = v;
    __shared__ float red[256];
    red[l] = v * v;
    __syncthreads();
    for (int s = 128; s > 0; s >>= 1) { if (l < s) red[l] += red[l + s]; __syncthreads(); }
    if (l == 0) g_enorm[k] = red[0];
}

// ---------------- weight prep: W[K][N] fp32 -> Wt[Npad][Kpad] fp16 h/l ----------------
__global__ void prep_w(const float* __restrict__ W, int K, int N, int Kpad, int Npad, unsigned off) {
    __shared__ float t[32][33];
    int k0 = blockIdx.x * 32, n0 = blockIdx.y * 32;
    int tx = threadIdx.x, ty = threadIdx.y;  // 32 x 8
    #pragma unroll
    for (int r = 0; r < 32; r += 8) {
        int k = k0 + ty + r, n = n0 + tx;
        t[ty + r][tx] = (k < K && n < N) ? W[(size_t)k * N + n] : 0.f;
    }
    __syncthreads();
    #pragma unroll
    for (int r = 0; r < 32; r += 8) {
        int n = n0 + ty + r, k = k0 + tx;
        if (n < Npad && k < Kpad) {
            __half h, l;
            split2(t[tx][ty + r], h, l);
            size_t o = off + (size_t)n * Kpad + k;
            g_wh[o] = h; g_wl[o] = l;
        }
    }
}

// ---------------- encoder input: [x | c | 0pad] -> fp16 h/l ----------------
__global__ void prep_xc(const float* __restrict__ x, const float* __restrict__ c) {
    int b = blockIdx.x, j = threadIdx.x;  // 576 threads
    float v = 0.f;
    if (j < FRAME)            v = x[(size_t)b * FRAME + j];
    else if (j < 2 * FRAME)   v = c[(size_t)b * FRAME + (j - FRAME)];
    __half h, l;
    split2(v, h, l);
    size_t o = (size_t)b * KP1 + j;
    g_sh[o] = h; g_sl[o] = l;
}

// =====================================================================
// fp16x2 tensor-core GEMM: C[128x128] = A[128 x Kpad] @ Wt^T   (Wt: [Npad][Kpad])
// NPROD 3: hh + hl + lh (~fp32).  NPROD 2: A fp16-only, hh + hl (~2^-12).
// MODE 0: relu + fp16(-split) out.  MODE 1: fp16-split out (no relu).
// MODE 2: fp32 out masked to N cols.
// cp.async 2-stage double buffering.
// =====================================================================
template<int MODE, int NPROD>
__global__ __launch_bounds__(256)
void mma_gemm(const __half* __restrict__ Ah, const __half* __restrict__ Al,
              int Kpad, unsigned woff, const float* __restrict__ bias, int N,
              __half* __restrict__ O0, __half* __restrict__ O1,
              float* __restrict__ Of, int ldo)
{
    extern __shared__ __align__(16) char smem[];
    const uint32_t sb = smem_u32(smem);
    const int tid = threadIdx.x, lane = tid & 31, wid = tid >> 5;
    const int warp_m = wid & 3, warp_n = wid >> 2;
    const int rowBlk = blockIdx.y * 128, colBlk = blockIdx.x * 128;
    constexpr uint32_t TILE = 128 * 72 * 2;      // 18432 B
    constexpr uint32_t NT_TILES = (NPROD == 3) ? 4 : 3;   // [Ah,(Al),Bh,Bl]
    constexpr uint32_t STAGE = NT_TILES * TILE;
    const uint32_t OS = 512;                     // after bias
    float* sbias = (float*)smem;

    if (tid < 128) {
        int gn = colBlk + tid;
        sbias[tid] = (gn < N) ? bias[gn] : 0.f;
    }

    const __half* Wh = g_wh + woff;
    const __half* Wl = g_wl + woff;

    // tile offsets within a stage
    constexpr uint32_t T_AH = 0;
    constexpr uint32_t T_AL = TILE;                       // only if NPROD==3
    constexpr uint32_t T_BH = (NPROD == 3) ? 2 * TILE : TILE;
    constexpr uint32_t T_BL = T_BH + TILE;

    auto load_chunk = [&](int kc, int st) {
        uint32_t base = sb + OS + (uint32_t)st * STAGE;
        #pragma unroll
        for (int it = 0; it < 4; it++) {
            int i = tid + it * 256;
            int r = i >> 3, q = i & 7;
            uint32_t off = (uint32_t)(r * 144 + q * 16);
            size_t ga = (size_t)(rowBlk + r) * Kpad + kc * 64 + q * 8;
            size_t gb = (size_t)(colBlk + r) * Kpad + kc * 64 + q * 8;
            cpa16(base + T_AH + off, Ah + ga);
            if (NPROD == 3) cpa16(base + T_AL + off, Al + ga);
            cpa16(base + T_BH + off, Wh + gb);
            cpa16(base + T_BL + off, Wl + gb);
        }
    };

    float acc[2][8][4];
    #pragma unroll
    for (int a = 0; a < 2; a++)
        #pragma unroll
        for (int b = 0; b < 8; b++)
            #pragma unroll
            for (int d = 0; d < 4; d++) acc[a][b][d] = 0.f;

    const int a_row  = (lane & 7) + ((lane >> 3) & 1) * 8;
    const int a_koff = ((lane >> 4) & 1) * 8;
    const int b_row  = (lane & 7) + ((lane >> 4) & 1) * 8;
    const int b_koff = ((lane >> 3) & 1) * 8;

    const int nch = Kpad >> 6;
    load_chunk(0, 0);
    CPA_COMMIT();

    for (int kc = 0; kc < nch; kc++) {
        if (kc + 1 < nch) load_chunk(kc + 1, (kc + 1) & 1);
        CPA_COMMIT();
        CPA_WAIT1();
        __syncthreads();
        const uint32_t stg = sb + OS + (uint32_t)(kc & 1) * STAGE;
        #pragma unroll
        for (int ks = 0; ks < 4; ks++) {
            uint32_t af[2][2][4];
            #pragma unroll
            for (int mt = 0; mt < 2; mt++) {
                ldsm4(af[0][mt], stg + T_AH +
                      (uint32_t)((warp_m * 32 + mt * 16 + a_row) * 72 + ks * 16 + a_koff) * 2);
                if (NPROD == 3)
                    ldsm4(af[1][mt], stg + T_AL +
                          (uint32_t)((warp_m * 32 + mt * 16 + a_row) * 72 + ks * 16 + a_koff) * 2);
            }
            #pragma unroll
            for (int nn = 0; nn < 4; nn++) {
                uint32_t bf[2][4];
                ldsm4(bf[0], stg + T_BH +
                      (uint32_t)((warp_n * 64 + nn * 16 + b_row) * 72 + ks * 16 + b_koff) * 2);
                ldsm4(bf[1], stg + T_BL +
                      (uint32_t)((warp_n * 64 + nn * 16 + b_row) * 72 + ks * 16 + b_koff) * 2);
                #pragma unroll
                for (int mt = 0; mt < 2; mt++)
                    #pragma unroll
                    for (int g = 0; g < 2; g++) {
                        float* c = acc[mt][nn * 2 + g];
                        mma16816(c, af[0][mt], bf[0][2 * g], bf[0][2 * g + 1]);   // hh
                        mma16816(c, af[0][mt], bf[1][2 * g], bf[1][2 * g + 1]);   // hl
                        if (NPROD == 3)
                            mma16816(c, af[1][mt], bf[0][2 * g], bf[0][2 * g + 1]); // lh
                    }
            }
        }
        __syncthreads();
    }

    // epilogue
    #pragma unroll
    for (int mt = 0; mt < 2; mt++) {
        const int row = rowBlk + warp_m * 32 + mt * 16 + (lane >> 2);
        #pragma unroll
        for (int g = 0; g < 8; g++) {
            const int colL = warp_n * 64 + g * 8 + 2 * (lane & 3);
            const int col = colBlk + colL;
            const float bz0 = sbias[colL], bz1 = sbias[colL + 1];
            const float* c = acc[mt][g];
            #pragma unroll
            for (int hf = 0; hf < 2; hf++) {
                const int r = row + hf * 8;
                float v0 = c[hf * 2] + bz0, v1 = c[hf * 2 + 1] + bz1;
                if (MODE == 0 || MODE == 1) {
                    if (MODE == 0) { v0 = fmaxf(v0, 0.f); v1 = fmaxf(v1, 0.f); }
                    size_t o = (size_t)r * ldo + col;
                    if (NPROD == 3) {
                        __half h0, l0, h1, l1;
                        split2(v0, h0, l0);
                        split2(v1, h1, l1);
                        *(uint32_t*)(O0 + o) = pack2(h0, h1);
                        *(uint32_t*)(O1 + o) = pack2(l0, l1);
                    } else {
                        *(uint32_t*)(O0 + o) = pack2(__float2half_rn(v0), __float2half_rn(v1));
                    }
                } else {
                    if (col < N)     Of[(size_t)r * ldo + col] = v0;
                    if (col + 1 < N) Of[(size_t)r * ldo + col + 1] = v1;
                }
            }
        }
    }
}

// =====================================================================
// VQ: per-row argmin over 1024 codes; dist = ||e||^2 - 2 mu.e
// mu A-tiles (2 splits x 4 chunks) resident in smem; embed B double-buffered.
// 256 threads, warp grid 4x2.  (3-product: argmin must match fp32)
// =====================================================================
__global__ __launch_bounds__(256)
void vq_kernel()
{
    extern __shared__ __align__(16) char smem[];
    const uint32_t sb = smem_u32(smem);
    const int tid = threadIdx.x, lane = tid & 31, wid = tid >> 5;
    const int warp_m = wid & 3, warp_n = wid >> 2;
    const int rowBlk = blockIdx.x * 128;
    constexpr uint32_t TILE = 128 * 72 * 2;
    float* sval = (float*)smem;                    // [128]
    int*   sidx = (int*)(smem + 512);              // [128]
    const uint32_t OA = 1024;                      // A: [s][kc] 8 tiles
    const uint32_t OB = OA + 8 * TILE;             // B: 2 stages x {h,l}

    const int a_row  = (lane & 7) + ((lane >> 3) & 1) * 8;
    const int a_koff = ((lane >> 4) & 1) * 8;
    const int b_row  = (lane & 7) + ((lane >> 4) & 1) * 8;
    const int b_koff = ((lane >> 3) & 1) * 8;

    // ---- preload resident A (mu splits), all 4 chunks ----
    #pragma unroll
    for (int kc = 0; kc < 4; kc++)
        #pragma unroll
        for (int it = 0; it < 4; it++) {
            int i = tid + it * 256;
            int r = i >> 3, q = i & 7;
            size_t ga = (size_t)(rowBlk + r) * LATENT + kc * 64 + q * 8;
            uint32_t dst = sb + OA + (uint32_t)kc * TILE + (uint32_t)(r * 144 + q * 16);
            cpa16(dst,            g_yh + ga);
            cpa16(dst + 4 * TILE, g_yl + ga);
        }
    CPA_COMMIT();

    auto load_b = [&](int ct, int kc, int st) {
        uint32_t base = sb + OB + (uint32_t)st * 2 * TILE;
        #pragma unroll
        for (int it = 0; it < 4; it++) {
            int i = tid + it * 256;
            int r = i >> 3, q = i & 7;
            size_t gb = OFF_EMB + (size_t)(ct * 128 + r) * LATENT + kc * 64 + q * 8;
            uint32_t dst = base + (uint32_t)(r * 144 + q * 16);
            cpa16(dst,        g_wh + gb);
            cpa16(dst + TILE, g_wl + gb);
        }
    };

    load_b(0, 0, 0);
    CPA_COMMIT();

    float bv[4];
    int   bi[4];
    #pragma unroll
    for (int s = 0; s < 4; s++) { bv[s] = 3.4e38f; bi[s] = 0; }

    int gstep = 0;
    for (int ct = 0; ct < 8; ct++) {
        float acc[2][8][4];
        #pragma unroll
        for (int a = 0; a < 2; a++)
            #pragma unroll
            for (int b = 0; b < 8; b++)
                #pragma unroll
                for (int d = 0; d < 4; d++) acc[a][b][d] = 0.f;

        for (int kc = 0; kc < 4; kc++) {
            int nct = (kc + 1 < 4) ? ct : ct + 1;
            int nkc = (kc + 1 < 4) ? kc + 1 : 0;
            if (nct < 8) load_b(nct, nkc, (gstep + 1) & 1);
            CPA_COMMIT();
            CPA_WAIT1();
            __syncthreads();
            const uint32_t stg = sb + OB + (uint32_t)(gstep & 1) * 2 * TILE;
            #pragma unroll
            for (int ks = 0; ks < 4; ks++) {
                uint32_t af[2][2][4];
                #pragma unroll
                for (int s = 0; s < 2; s++)
                    #pragma unroll
                    for (int mt = 0; mt < 2; mt++)
                        ldsm4(af[s][mt], sb + OA + (uint32_t)(s * 4 + kc) * TILE +
                              (uint32_t)((warp_m * 32 + mt * 16 + a_row) * 72 + ks * 16 + a_koff) * 2);
                #pragma unroll
                for (int nn = 0; nn < 4; nn++) {
                    uint32_t bf[2][4];
                    #pragma unroll
                    for (int s = 0; s < 2; s++)
                        ldsm4(bf[s], stg + s * TILE +
                              (uint32_t)((warp_n * 64 + nn * 16 + b_row) * 72 + ks * 16 + b_koff) * 2);
                    #pragma unroll
                    for (int mt = 0; mt < 2; mt++)
                        #pragma unroll
                        for (int g = 0; g < 2; g++) {
                            float* c = acc[mt][nn * 2 + g];
                            mma16816(c, af[0][mt], bf[0][2 * g], bf[0][2 * g + 1]);
                            mma16816(c, af[0][mt], bf[1][2 * g], bf[1][2 * g + 1]);
                            mma16816(c, af[1][mt], bf[0][2 * g], bf[0][2 * g + 1]);
                        }
                }
            }
            gstep++;
            __syncthreads();
        }

        // ---- argmin epilogue for this code tile ----
        #pragma unroll
        for (int mt = 0; mt < 2; mt++)
            #pragma unroll
            for (int hf = 0; hf < 2; hf++) {
                const int slot = mt * 2 + hf;
                const int rowL = warp_m * 32 + mt * 16 + hf * 8 + (lane >> 2);
                float v = 3.4e38f; int idx = 0;
                #pragma unroll
                for (int g = 0; g < 8; g++)
                    #pragma unroll
                    for (int j = 0; j < 2; j++) {
                        int colL = warp_n * 64 + g * 8 + 2 * (lane & 3) + j;
                        int code = ct * 128 + colL;
                        float d = g_enorm[code] - 2.f * acc[mt][g][hf * 2 + j];
                        if (d < v || (d == v && code < idx)) { v = d; idx = code; }
                    }
                #pragma unroll
                for (int o = 1; o <= 2; o <<= 1) {
                    float ov = __shfl_xor_sync(0xFFFFFFFFu, v, o);
                    int   oi = __shfl_xor_sync(0xFFFFFFFFu, idx, o);
                    if (ov < v || (ov == v && oi < idx)) { v = ov; idx = oi; }
                }
                if (warp_n == 1 && (lane & 3) == 0) { sval[rowL] = v; sidx[rowL] = idx; }
                __syncthreads();
                if (warp_n == 0 && (lane & 3) == 0) {
                    float ov = sval[rowL]; int oi = sidx[rowL];
                    if (ov < v || (ov == v && oi < idx)) { v = ov; idx = oi; }
                    if (v < bv[slot] || (v == bv[slot] && idx < bi[slot])) { bv[slot] = v; bi[slot] = idx; }
                }
                __syncthreads();
            }
    }

    if (warp_n == 0 && (lane & 3) == 0) {
        #pragma unroll
        for (int mt = 0; mt < 2; mt++)
            #pragma unroll
            for (int hf = 0; hf < 2; hf++) {
                const int slot = mt * 2 + hf;
                const int rowL = warp_m * 32 + mt * 16 + hf * 8 + (lane >> 2);
                g_ind[rowBlk + rowL] = bi[slot];
                atomicAdd(&g_counts[bi[slot]], 1u);
            }
    }
}

// ---------------- gather quantize -> decoder input [q | c | 0pad] + loss ----------------
// decoder is 2-product (A fp16-only): write g_sh only.
__global__ void gather_kernel(const float* __restrict__ c) {
    int b = blockIdx.x, j = threadIdx.x;   // 576 threads
    __shared__ float red[256];
    int k = g_ind[b];
    float v = 0.f;
    if (j < LATENT) {
        size_t om = (size_t)b * LATENT + j;
        float m = __half2float(g_yh[om]) + __half2float(g_yl[om]);
        float q = g_embTf[k * LATENT + j];
        float d = q - m;
        red[j] = d * d;
        v = q;
    } else if (j < LATENT + FRAME) {
        v = c[(size_t)b * FRAME + (j - LATENT)];
    }
    g_sh[(size_t)b * KP1 + j] = __float2half_rn(v);
    __syncthreads();
    for (int s = 128; s > 0; s >>= 1) { if (j < s) red[j] += red[j + s]; __syncthreads(); }
    if (j == 0) atomicAdd(&g_loss, (double)red[0]);
}

// ---------------- finalize scalars ----------------
__global__ void finalize_kernel(float* __restrict__ out) {
    __shared__ double red[1024];
    int t = threadIdx.x;
    double p = (double)g_counts[t] / (double)BATCH;
    red[t] = p * log(p + 1e-10);
    __syncthreads();
    for (int s = 512; s > 0; s >>= 1) { if (t < s) red[t] += red[t + s]; __syncthreads(); }
    if (t == 0) {
        size_t off = (size_t)BATCH * FRAME;
        out[off]     = (float)(g_loss / ((double)BATCH * (double)LATENT));
        out[off + 1] = (float)exp(-red[0]);
    }
}

// ---------------- launch ----------------
extern "C" void kernel_launch(void* const* d_in, const int* in_sizes, int n_in,
                              void* d_out, int out_size)
{
    const float* x    = (const float*)d_in[0];
    const float* c    = (const float*)d_in[1];
    const float* W1   = (const float*)d_in[2];  const float* b1  = (const float*)d_in[3];
    const float* W2   = (const float*)d_in[4];  const float* b2  = (const float*)d_in[5];
    const float* W3   = (const float*)d_in[6];  const float* b3  = (const float*)d_in[7];
    const float* Wmu  = (const float*)d_in[8];  const float* bmu = (const float*)d_in[9];
    const float* W4   = (const float*)d_in[10]; const float* b4  = (const float*)d_in[11];
    const float* W5   = (const float*)d_in[12]; const float* b5  = (const float*)d_in[13];
    const float* W6   = (const float*)d_in[14]; const float* b6  = (const float*)d_in[15];
    const float* Wo   = (const float*)d_in[16]; const float* bo  = (const float*)d_in[17];
    const float* embed= (const float*)d_in[18];
    float* out = (float*)d_out;

    __half *sh, *sl, *xh, *xl, *yh, *yl;
    cudaGetSymbolAddress((void**)&sh, g_sh);
    cudaGetSymbolAddress((void**)&sl, g_sl);
    cudaGetSymbolAddress((void**)&xh, g_xh);
    cudaGetSymbolAddress((void**)&xl, g_xl);
    cudaGetSymbolAddress((void**)&yh, g_yh);
    cudaGetSymbolAddress((void**)&yl, g_yl);

    const int SMG3 = 512 + 2 * 4 * 18432;              // 147968 (1 CTA/SM)
    const int SMG2 = 512 + 2 * 3 * 18432;              // 111104 (2 CTA/SM)
    const int SMV  = 1024 + 8 * 18432 + 2 * 2 * 18432; // 222208
    cudaFuncSetAttribute((const void*)mma_gemm<0, 3>, cudaFuncAttributeMaxDynamicSharedMemorySize, SMG3);
    cudaFuncSetAttribute((const void*)mma_gemm<1, 3>, cudaFuncAttributeMaxDynamicSharedMemorySize, SMG3);
    cudaFuncSetAttribute((const void*)mma_gemm<0, 2>, cudaFuncAttributeMaxDynamicSharedMemorySize, SMG2);
    cudaFuncSetAttribute((const void*)mma_gemm<2, 2>, cudaFuncAttributeMaxDynamicSharedMemorySize, SMG2);
    cudaFuncSetAttribute((const void*)vq_kernel,      cudaFuncAttributeMaxDynamicSharedMemorySize, SMV);

    const int MT = BATCH / 128;   // 1024 row tiles
    dim3 tb(32, 8);

    init_kernel<<<1, 1024>>>();
    enorm_kernel<<<KCODES, 256>>>(embed);

    // weight prep (transpose + fp16 2-way split), grid = (Kpad/32, Npad/32)
    prep_w<<<dim3(18, 16), tb>>>(W1,  534, 512,  KP1, 512,  OFF_W1);
    prep_w<<<dim3(16, 16), tb>>>(W2,  512, 512,  512, 512,  OFF_W2);
    prep_w<<<dim3(16, 16), tb>>>(W3,  512, 512,  512, 512,  OFF_W3);
    prep_w<<<dim3(16, 8),  tb>>>(Wmu, 512, 256,  512, 256,  OFF_WMU);
    prep_w<<<dim3(18, 16), tb>>>(W4,  523, 512,  KP1, 512,  OFF_W4);
    prep_w<<<dim3(16, 16), tb>>>(W5,  512, 512,  512, 512,  OFF_W5);
    prep_w<<<dim3(16, 16), tb>>>(W6,  512, 512,  512, 512,  OFF_W6);
    prep_w<<<dim3(16, 12), tb>>>(Wo,  512, 267,  512, 384,  OFF_WO);
    prep_w<<<dim3(8,  32), tb>>>(embed, 256, 1024, 256, 1024, OFF_EMB);

    prep_xc<<<BATCH, KP1>>>(x, c);

    // encoder (3-product: mu must match fp32 for exact argmin)
    mma_gemm<0, 3><<<dim3(4, MT), 256, SMG3>>>(sh, sl, KP1, OFF_W1,  b1,  512, xh, xl, nullptr, 512);
    mma_gemm<0, 3><<<dim3(4, MT), 256, SMG3>>>(xh, xl, 512, OFF_W2,  b2,  512, yh, yl, nullptr, 512);
    mma_gemm<0, 3><<<dim3(4, MT), 256, SMG3>>>(yh, yl, 512, OFF_W3,  b3,  512, xh, xl, nullptr, 512);
    mma_gemm<1, 3><<<dim3(2, MT), 256, SMG3>>>(xh, xl, 512, OFF_WMU, bmu, 256, yh, yl, nullptr, 256);  // mu splits

    // vector quantizer + gather/loss (rebuilds g_sh as decoder input)
    vq_kernel<<<MT, 256, SMV>>>();
    gather_kernel<<<BATCH, KP1>>>(c);

    // decoder (2-product: A fp16, hh+hl; error ~2^-12 direct to output)
    mma_gemm<0, 2><<<dim3(4, MT), 256, SMG2>>>(sh, nullptr, KP1, OFF_W4, b4, 512, xh, nullptr, nullptr, 512);
    mma_gemm<0, 2><<<dim3(4, MT), 256, SMG2>>>(xh, nullptr, 512, OFF_W5, b5, 512, yh, nullptr, nullptr, 512);
    mma_gemm<0, 2><<<dim3(4, MT), 256, SMG2>>>(yh, nullptr, 512, OFF_W6, b6, 512, xh, nullptr, nullptr, 512);
    mma_gemm<2, 2><<<dim3(3, MT), 256, SMG2>>>(xh, nullptr, 512, OFF_WO, bo, 267, nullptr, nullptr, out, FRAME);

    finalize_kernel<<<1, 1024>>>(out);
}